// round 6
// baseline (speedup 1.0000x reference)
#include <cuda_runtime.h>
#include <cuda_bf16.h>
#include <math.h>
#include <stdint.h>

#define B_SZ   2048
#define K_OBJ  16
#define ROWS   (B_SZ * K_OBJ)      // 32768
#define NPAIR  120

typedef __nv_bfloat16 bf16;

// ---------------- scratch (device globals; no allocation allowed) ----------------
__device__ __align__(16) bf16 g_z_hi  [(size_t)ROWS * 128];
__device__ __align__(16) bf16 g_z_lo  [(size_t)ROWS * 128];
__device__ __align__(16) bf16 g_h0_hi [(size_t)ROWS * 128];
__device__ __align__(16) bf16 g_h0_lo [(size_t)ROWS * 128];
__device__ __align__(16) bf16 g_ze_hi [(size_t)ROWS * 256];
__device__ __align__(16) bf16 g_ze_lo [(size_t)ROWS * 256];
__device__ __align__(16) bf16 g_h_hi  [(size_t)ROWS * 128];
__device__ __align__(16) bf16 g_h_lo  [(size_t)ROWS * 128];
__device__ __align__(16) bf16 g_E_hi  [(size_t)ROWS * 512];
__device__ __align__(16) bf16 g_E_lo  [(size_t)ROWS * 512];
__device__ __align__(16) bf16 g_rel_hi[(size_t)ROWS * 128];
__device__ __align__(16) bf16 g_rel_lo[(size_t)ROWS * 128];
__device__ __align__(16) float g_gi [(size_t)ROWS * 384];
__device__ __align__(16) float g_gh [(size_t)ROWS * 384];
__device__ __align__(16) float g_UV [(size_t)ROWS * 1024];
__device__ __align__(16) bf16 g_Wobj_hi[256 * 128],  g_Wobj_lo[256 * 128];
__device__ __align__(16) bf16 g_Wih_hi [384 * 256],  g_Wih_lo [384 * 256];
__device__ __align__(16) bf16 g_Whh_hi [384 * 128],  g_Whh_lo [384 * 128];
__device__ __align__(16) bf16 g_WUV_hi [1024 * 128], g_WUV_lo [1024 * 128];
__device__ __align__(16) bf16 g_WcE_hi [128 * 640],  g_WcE_lo [128 * 640];
__device__ __align__(16) bf16 g_Wstk_hi[384 * 128],  g_Wstk_lo[384 * 128];
__device__ __align__(16) float g_bstk[384];

// ---------------- helpers ----------------
__device__ __forceinline__ void bf16split(float x, bf16& h, bf16& l) {
    h = __float2bfloat16_rn(x);
    l = __float2bfloat16_rn(x - __bfloat162float(h));
}

__device__ __forceinline__ uint32_t smem_u32(const void* p) {
    uint32_t a;
    asm("{ .reg .u64 t; cvta.to.shared.u64 t, %1; cvt.u32.u64 %0, t; }" : "=r"(a) : "l"(p));
    return a;
}

__device__ __forceinline__ void cp16(uint32_t dst, const void* src) {
    asm volatile("cp.async.ca.shared.global [%0], [%1], 16;" :: "r"(dst), "l"(src) : "memory");
}
#define CP_COMMIT() asm volatile("cp.async.commit_group;" ::: "memory")
#define CP_WAIT(n)  asm volatile("cp.async.wait_group %0;" :: "n"(n) : "memory")

__device__ __forceinline__ void mma16(float* d, const uint32_t* a, const uint32_t* b) {
    asm volatile(
        "mma.sync.aligned.m16n8k16.row.col.f32.bf16.bf16.f32 "
        "{%0,%1,%2,%3}, {%4,%5,%6,%7}, {%8,%9}, {%0,%1,%2,%3};"
        : "+f"(d[0]), "+f"(d[1]), "+f"(d[2]), "+f"(d[3])
        : "r"(a[0]), "r"(a[1]), "r"(a[2]), "r"(a[3]), "r"(b[0]), "r"(b[1]));
}

// ---------------- tensor-core bf16x3 NT GEMM, 4-stage pipeline ----------------
// C[M,N] = act(X @ W^T + bias); X split at k1 between X1/X2; W [N,Kd] row-major bf16 hi/lo.
// CTA tile 128x128, K-slab 16, 4-stage cp.async ring, ONE barrier per slab.
// OUTM: 0 = f32 C; 1 = bf16-split (Chi, Clo); 2 = final f32 (n<256 -> C ld256, else C2 ld128).
#define PADW 12
#define TILE_WORDS 1536    // 128 * PADW
#define STG_WORDS  6144    // 4 tiles * TILE_WORDS
#define NSTG 4

template <int ACT, int OUTM>
__global__ void __launch_bounds__(256, 2) gemm_mma(
    const bf16* __restrict__ X1hi, const bf16* __restrict__ X1lo, int ld1, int k1,
    const bf16* __restrict__ X2hi, const bf16* __restrict__ X2lo, int ld2,
    const bf16* __restrict__ Whi, const bf16* __restrict__ Wlo,
    const float* __restrict__ bias,
    float* __restrict__ C, bf16* __restrict__ Chi, bf16* __restrict__ Clo,
    int ldc, float* __restrict__ C2, int Kd)
{
    extern __shared__ uint32_t smw[];
    const uint32_t sb = smem_u32(smw);

    const int tid = threadIdx.x;
    const int lane = tid & 31;
    const int wid = tid >> 5;
    const int warp_m = wid >> 1;
    const int warp_n = wid & 1;
    const int gid = lane >> 2;
    const int tig = lane & 3;
    const int bm = blockIdx.y * 128;
    const int bn = blockIdx.x * 128;

    float acc[2][8][4];
#pragma unroll
    for (int mi = 0; mi < 2; mi++)
#pragma unroll
        for (int nf = 0; nf < 8; nf++)
#pragma unroll
            for (int e = 0; e < 4; e++) acc[mi][nf][e] = 0.f;

    const int lm = tid >> 1;            // row 0..127
    const int lk = (tid & 1) * 8;       // k-elem offset 0 or 8
    const uint32_t so = (uint32_t)(lm * PADW + (tid & 1) * 4) * 4;

    auto load_slab = [&](int k0, int s) {
        const bf16 *ahi, *alo; int xld, xc;
        if (k0 < k1) { ahi = X1hi; alo = X1lo; xld = ld1; xc = k0; }
        else         { ahi = X2hi; alo = X2lo; xld = ld2; xc = k0 - k1; }
        const uint32_t st = sb + s * (STG_WORDS * 4);
        const size_t ga = (size_t)(bm + lm) * xld + xc + lk;
        const size_t gw = (size_t)(bn + lm) * Kd + k0 + lk;
        cp16(st + so,                   ahi + ga);
        cp16(st + TILE_WORDS * 4 + so,  alo + ga);
        cp16(st + TILE_WORDS * 8 + so,  Whi + gw);
        cp16(st + TILE_WORDS * 12 + so, Wlo + gw);
    };

    const int nIter = Kd / 16;
#pragma unroll
    for (int p = 0; p < NSTG - 1; p++) {
        if (p < nIter) load_slab(p * 16, p);
        CP_COMMIT();
    }

#pragma unroll 1
    for (int i = 0; i < nIter; i++) {
        CP_WAIT(NSTG - 2);     // slabs 0..i complete
        __syncthreads();
        if (i + NSTG - 1 < nIter) load_slab((i + NSTG - 1) * 16, (i + NSTG - 1) & (NSTG - 1));
        CP_COMMIT();

        const int s = i & (NSTG - 1);
        const uint32_t* sA  = smw + s * STG_WORDS;
        const uint32_t* sAl = sA + TILE_WORDS;
        const uint32_t* sB  = sA + 2 * TILE_WORDS;
        const uint32_t* sBl = sA + 3 * TILE_WORDS;

        uint32_t ah[2][4], al[2][4];
#pragma unroll
        for (int mi = 0; mi < 2; mi++) {
            int am = (warp_m * 32 + mi * 16 + gid) * PADW;
            ah[mi][0] = sA [am + tig];
            ah[mi][1] = sA [am + 8 * PADW + tig];
            ah[mi][2] = sA [am + tig + 4];
            ah[mi][3] = sA [am + 8 * PADW + tig + 4];
            al[mi][0] = sAl[am + tig];
            al[mi][1] = sAl[am + 8 * PADW + tig];
            al[mi][2] = sAl[am + tig + 4];
            al[mi][3] = sAl[am + 8 * PADW + tig + 4];
        }
        uint32_t bf[8][2];
#pragma unroll
        for (int nf = 0; nf < 8; nf++) {
            int an = (warp_n * 64 + nf * 8 + gid) * PADW;
            bf[nf][0] = sB[an + tig];
            bf[nf][1] = sB[an + tig + 4];
        }
#pragma unroll
        for (int mi = 0; mi < 2; mi++)
#pragma unroll
            for (int nf = 0; nf < 8; nf++) {
                mma16(acc[mi][nf], ah[mi], bf[nf]);
                mma16(acc[mi][nf], al[mi], bf[nf]);
            }
#pragma unroll
        for (int nf = 0; nf < 8; nf++) {
            int an = (warp_n * 64 + nf * 8 + gid) * PADW;
            bf[nf][0] = sBl[an + tig];
            bf[nf][1] = sBl[an + tig + 4];
        }
#pragma unroll
        for (int mi = 0; mi < 2; mi++)
#pragma unroll
            for (int nf = 0; nf < 8; nf++)
                mma16(acc[mi][nf], ah[mi], bf[nf]);
    }

    // ---- epilogue ----
    float* outp = C; int oldc = ldc, ncol0 = bn;
    if (OUTM == 2) {
        if (bn >= 256) { outp = C2; oldc = 128; ncol0 = bn - 256; }
        else           { outp = C;  oldc = 256; ncol0 = bn; }
    }

#pragma unroll
    for (int mi = 0; mi < 2; mi++) {
        int r0 = bm + warp_m * 32 + mi * 16 + gid;
#pragma unroll
        for (int nf = 0; nf < 8; nf++) {
            int cg = bn + warp_n * 64 + nf * 8 + tig * 2;
            int cl = ncol0 + warp_n * 64 + nf * 8 + tig * 2;
            float b0 = 0.f, b1 = 0.f;
            if (bias) { float2 bv = *(const float2*)(bias + cg); b0 = bv.x; b1 = bv.y; }
            float v00 = acc[mi][nf][0] + b0;
            float v01 = acc[mi][nf][1] + b1;
            float v10 = acc[mi][nf][2] + b0;
            float v11 = acc[mi][nf][3] + b1;
            if (ACT == 1) {
                v00 = (v00 > 0.f) ? v00 : expm1f(v00);
                v01 = (v01 > 0.f) ? v01 : expm1f(v01);
                v10 = (v10 > 0.f) ? v10 : expm1f(v10);
                v11 = (v11 > 0.f) ? v11 : expm1f(v11);
            }
            if (OUTM == 1) {
                bf16 h, l;
                __nv_bfloat162 ph0, pl0, ph1, pl1;
                bf16split(v00, h, l); ph0.x = h; pl0.x = l;
                bf16split(v01, h, l); ph0.y = h; pl0.y = l;
                bf16split(v10, h, l); ph1.x = h; pl1.x = l;
                bf16split(v11, h, l); ph1.y = h; pl1.y = l;
                *(__nv_bfloat162*)(Chi + (size_t)r0 * ldc + cl)       = ph0;
                *(__nv_bfloat162*)(Clo + (size_t)r0 * ldc + cl)       = pl0;
                *(__nv_bfloat162*)(Chi + (size_t)(r0 + 8) * ldc + cl) = ph1;
                *(__nv_bfloat162*)(Clo + (size_t)(r0 + 8) * ldc + cl) = pl1;
            } else {
                *(float2*)(outp + (size_t)r0 * oldc + cl)       = make_float2(v00, v01);
                *(float2*)(outp + (size_t)(r0 + 8) * oldc + cl) = make_float2(v10, v11);
            }
        }
    }
}

// ---------------- split / prep kernels ----------------
__global__ void split_f32(const float* __restrict__ src, bf16* __restrict__ hi,
                          bf16* __restrict__ lo, int n) {
    int idx = blockIdx.x * blockDim.x + threadIdx.x;
    if (idx >= n) return;
    bf16 h, l;
    bf16split(src[idx], h, l);
    hi[idx] = h; lo[idx] = l;
}

__global__ void prep_wuv(const float* __restrict__ We) {
    int idx = blockIdx.x * blockDim.x + threadIdx.x;
    if (idx >= 1024 * 128) return;
    int n = idx >> 7, c = idx & 127;
    float v;
    if (n < 512) v = We[n * 512 + c] + We[n * 512 + 128 + c];
    else {
        int nn = n - 512;
        v = We[nn * 512 + 256 + c] + We[nn * 512 + 384 + c];
    }
    bf16 h, l; bf16split(v, h, l);
    g_WUV_hi[idx] = h; g_WUV_lo[idx] = l;
}

__global__ void prep_wc(const float* __restrict__ Wc) {
    int idx = blockIdx.x * blockDim.x + threadIdx.x;
    if (idx >= 128 * 640) return;
    int n = idx / 640, c = idx % 640;
    float v = (c < 128) ? (Wc[n * 768 + c] + Wc[n * 768 + 128 + c])
                        : Wc[n * 768 + 128 + c];
    bf16 h, l; bf16split(v, h, l);
    g_WcE_hi[idx] = h; g_WcE_lo[idx] = l;
}

__global__ void prep_wstk(const float* __restrict__ Wl, const float* __restrict__ bl,
                          const float* __restrict__ Wsc, const float* __restrict__ bs,
                          const float* __restrict__ Wh, const float* __restrict__ bh) {
    int idx = blockIdx.x * blockDim.x + threadIdx.x;
    if (idx < 384 * 128) {
        int n = idx >> 7, c = idx & 127;
        const float* W = (n < 128) ? Wl : ((n < 256) ? Wsc : Wh);
        bf16 h, l; bf16split(W[(n & 127) * 128 + c], h, l);
        g_Wstk_hi[idx] = h; g_Wstk_lo[idx] = l;
    }
    if (idx < 384) {
        const float* bb = (idx < 128) ? bl : ((idx < 256) ? bs : bh);
        g_bstk[idx] = bb[idx & 127];
    }
}

// ---------------- GRU gate fusion (writes split h) ----------------
__device__ __forceinline__ float sigm(float x) { return 1.f / (1.f + expf(-x)); }

__global__ void gru_gate(const float* __restrict__ gi, const float* __restrict__ gh,
                         const float* __restrict__ h0,
                         bf16* __restrict__ hhi, bf16* __restrict__ hlo) {
    int idx = blockIdx.x * blockDim.x + threadIdx.x;
    if (idx >= ROWS * 128) return;
    int m = idx >> 7, c = idx & 127;
    const float* gim = gi + (size_t)m * 384;
    const float* ghm = gh + (size_t)m * 384;
    float r = sigm(gim[c] + ghm[c]);
    float u = sigm(gim[128 + c] + ghm[128 + c]);
    float n = tanhf(gim[256 + c] + r * ghm[256 + c]);
    float v = (1.f - u) * n + u * h0[idx];
    bf16 h, l; bf16split(v, h, l);
    hhi[idx] = h; hlo[idx] = l;
}

// ---------------- pair stage (writes split E) ----------------
__global__ void __launch_bounds__(512) pair_kernel(
    const float* __restrict__ UV, const float* __restrict__ Wa,
    const float* __restrict__ ba, const float* __restrict__ be,
    bf16* __restrict__ Ehi, bf16* __restrict__ Elo)
{
    extern __shared__ float smf[];
    float* Ub  = smf;
    float* Vb  = Ub + 16 * 512;
    float* Eb  = Vb + 16 * 512;
    float* was = Eb + 16 * 512;
    float* bes = was + 512;

    const int b = blockIdx.x;
    const int tid = threadIdx.x;

    for (int i = tid; i < 16 * 512; i += 512) {
        int k = i >> 9, t = i & 511;
        const float* row = UV + (size_t)(b * 16 + k) * 1024;
        Ub[i] = row[t];
        Vb[i] = row[512 + t];
        Eb[i] = 0.f;
    }
    was[tid & 511] = Wa[tid & 511];
    bes[tid & 511] = be[tid & 511];
    __syncthreads();

    const float ba0 = ba[0];
    const int wid = tid >> 5, lane = tid & 31;

    for (int p = wid; p < NPAIR; p += 16) {
        int ii = 0, rem = p, span = K_OBJ - 1;
        while (rem >= span) { rem -= span; ii++; span--; }
        int jj = ii + 1 + rem;

        const float* Ui = Ub + ii * 512;
        const float* Vj = Vb + jj * 512;
        float e[16];
        float dot = 0.f;
#pragma unroll
        for (int c = 0; c < 16; c++) {
            int t = lane + 32 * c;
            float x = Ui[t] + Vj[t] + bes[t];
            x = (x > 0.f) ? x : expm1f(x);
            e[c] = x;
            dot += x * was[t];
        }
#pragma unroll
        for (int o = 16; o > 0; o >>= 1) dot += __shfl_xor_sync(0xffffffffu, dot, o);
        float att = 1.f / (1.f + expf(-(dot + ba0)));

        float* Ei = Eb + ii * 512;
        float* Ej = Eb + jj * 512;
#pragma unroll
        for (int c = 0; c < 16; c++) {
            int t = lane + 32 * c;
            float w = att * e[c];
            atomicAdd(Ei + t, w);
            atomicAdd(Ej + t, w);
        }
    }
    __syncthreads();

    bf16* Eh = Ehi + (size_t)b * 16 * 512;
    bf16* El = Elo + (size_t)b * 16 * 512;
    for (int i = tid; i < 16 * 512; i += 512) {
        bf16 h, l; bf16split(Eb[i], h, l);
        Eh[i] = h; El[i] = l;
    }
}

// ---------------- host launcher ----------------
extern "C" void kernel_launch(void* const* d_in, const int* in_sizes, int n_in,
                              void* d_out, int out_size)
{
    const float* z    = (const float*)d_in[0];
    const float* h0   = (const float*)d_in[1];
    const float* W_obj= (const float*)d_in[2];
    const float* b_obj= (const float*)d_in[3];
    const float* Wih  = (const float*)d_in[4];
    const float* bih  = (const float*)d_in[5];
    const float* Whh  = (const float*)d_in[6];
    const float* bhh  = (const float*)d_in[7];
    const float* We   = (const float*)d_in[8];
    const float* be   = (const float*)d_in[9];
    const float* Wa   = (const float*)d_in[10];
    const float* ba   = (const float*)d_in[11];
    const float* Wc   = (const float*)d_in[12];
    const float* bc   = (const float*)d_in[13];
    const float* Wl   = (const float*)d_in[14];
    const float* bl   = (const float*)d_in[15];
    const float* Wsc  = (const float*)d_in[16];
    const float* bs   = (const float*)d_in[17];
    const float* Wh   = (const float*)d_in[18];
    const float* bh   = (const float*)d_in[19];

    float* out1 = (float*)d_out;                 // [ROWS, 256] = concat(loc, scale)
    float* out2 = out1 + (size_t)ROWS * 256;     // [ROWS, 128] = h_out

    bf16 *p_z_hi, *p_z_lo, *p_h0_hi, *p_h0_lo, *p_ze_hi, *p_ze_lo;
    bf16 *p_h_hi, *p_h_lo, *p_E_hi, *p_E_lo, *p_rel_hi, *p_rel_lo;
    float *p_gi, *p_gh, *p_UV, *p_bstk;
    bf16 *p_Wobj_hi, *p_Wobj_lo, *p_Wih_hi, *p_Wih_lo, *p_Whh_hi, *p_Whh_lo;
    bf16 *p_WUV_hi, *p_WUV_lo, *p_WcE_hi, *p_WcE_lo, *p_Wstk_hi, *p_Wstk_lo;

    cudaGetSymbolAddress((void**)&p_z_hi,  g_z_hi);   cudaGetSymbolAddress((void**)&p_z_lo,  g_z_lo);
    cudaGetSymbolAddress((void**)&p_h0_hi, g_h0_hi);  cudaGetSymbolAddress((void**)&p_h0_lo, g_h0_lo);
    cudaGetSymbolAddress((void**)&p_ze_hi, g_ze_hi);  cudaGetSymbolAddress((void**)&p_ze_lo, g_ze_lo);
    cudaGetSymbolAddress((void**)&p_h_hi,  g_h_hi);   cudaGetSymbolAddress((void**)&p_h_lo,  g_h_lo);
    cudaGetSymbolAddress((void**)&p_E_hi,  g_E_hi);   cudaGetSymbolAddress((void**)&p_E_lo,  g_E_lo);
    cudaGetSymbolAddress((void**)&p_rel_hi,g_rel_hi); cudaGetSymbolAddress((void**)&p_rel_lo,g_rel_lo);
    cudaGetSymbolAddress((void**)&p_gi, g_gi);
    cudaGetSymbolAddress((void**)&p_gh, g_gh);
    cudaGetSymbolAddress((void**)&p_UV, g_UV);
    cudaGetSymbolAddress((void**)&p_bstk, g_bstk);
    cudaGetSymbolAddress((void**)&p_Wobj_hi, g_Wobj_hi); cudaGetSymbolAddress((void**)&p_Wobj_lo, g_Wobj_lo);
    cudaGetSymbolAddress((void**)&p_Wih_hi,  g_Wih_hi);  cudaGetSymbolAddress((void**)&p_Wih_lo,  g_Wih_lo);
    cudaGetSymbolAddress((void**)&p_Whh_hi,  g_Whh_hi);  cudaGetSymbolAddress((void**)&p_Whh_lo,  g_Whh_lo);
    cudaGetSymbolAddress((void**)&p_WUV_hi,  g_WUV_hi);  cudaGetSymbolAddress((void**)&p_WUV_lo,  g_WUV_lo);
    cudaGetSymbolAddress((void**)&p_WcE_hi,  g_WcE_hi);  cudaGetSymbolAddress((void**)&p_WcE_lo,  g_WcE_lo);
    cudaGetSymbolAddress((void**)&p_Wstk_hi, g_Wstk_hi); cudaGetSymbolAddress((void**)&p_Wstk_lo, g_Wstk_lo);

    const int SMEM_GEMM = NSTG * STG_WORDS * 4;   // 98304
    cudaFuncSetAttribute(gemm_mma<1,1>, cudaFuncAttributeMaxDynamicSharedMemorySize, SMEM_GEMM);
    cudaFuncSetAttribute(gemm_mma<0,0>, cudaFuncAttributeMaxDynamicSharedMemorySize, SMEM_GEMM);
    cudaFuncSetAttribute(gemm_mma<0,1>, cudaFuncAttributeMaxDynamicSharedMemorySize, SMEM_GEMM);
    cudaFuncSetAttribute(gemm_mma<0,2>, cudaFuncAttributeMaxDynamicSharedMemorySize, SMEM_GEMM);

    // input + weight splits
    split_f32<<<(ROWS * 128 + 255) / 256, 256>>>(z, p_z_hi, p_z_lo, ROWS * 128);
    split_f32<<<(ROWS * 128 + 255) / 256, 256>>>(h0, p_h0_hi, p_h0_lo, ROWS * 128);
    split_f32<<<(256 * 128 + 255) / 256, 256>>>(W_obj, p_Wobj_hi, p_Wobj_lo, 256 * 128);
    split_f32<<<(384 * 256 + 255) / 256, 256>>>(Wih, p_Wih_hi, p_Wih_lo, 384 * 256);
    split_f32<<<(384 * 128 + 255) / 256, 256>>>(Whh, p_Whh_hi, p_Whh_lo, 384 * 128);
    prep_wuv <<<(1024 * 128 + 255) / 256, 256>>>(We);
    prep_wc  <<<(128 * 640 + 255) / 256, 256>>>(Wc);
    prep_wstk<<<(384 * 128 + 255) / 256, 256>>>(Wl, bl, Wsc, bs, Wh, bh);

    const int MB = ROWS / 128;   // 256

    // G1: z_embed = elu(z @ W_obj^T + b_obj) -> split  [ROWS, 256]
    gemm_mma<1,1><<<dim3(2, MB), 256, SMEM_GEMM>>>(
        p_z_hi, p_z_lo, 128, 128, nullptr, nullptr, 0,
        p_Wobj_hi, p_Wobj_lo, b_obj, nullptr, p_ze_hi, p_ze_lo, 256, nullptr, 128);
    // G2a: gi = z_embed @ Wih^T + bih  [ROWS, 384] f32
    gemm_mma<0,0><<<dim3(3, MB), 256, SMEM_GEMM>>>(
        p_ze_hi, p_ze_lo, 256, 256, nullptr, nullptr, 0,
        p_Wih_hi, p_Wih_lo, bih, p_gi, nullptr, nullptr, 384, nullptr, 256);
    // G2b: gh = h0 @ Whh^T + bhh  [ROWS, 384] f32
    gemm_mma<0,0><<<dim3(3, MB), 256, SMEM_GEMM>>>(
        p_h0_hi, p_h0_lo, 128, 128, nullptr, nullptr, 0,
        p_Whh_hi, p_Whh_lo, bhh, p_gh, nullptr, nullptr, 384, nullptr, 128);
    // GRU gates -> h (split)
    gru_gate<<<(ROWS * 128 + 255) / 256, 256>>>(p_gi, p_gh, h0, p_h_hi, p_h_lo);

    // G3: UV = h @ W_UV^T  [ROWS, 1024] f32
    gemm_mma<0,0><<<dim3(8, MB), 256, SMEM_GEMM>>>(
        p_h_hi, p_h_lo, 128, 128, nullptr, nullptr, 0,
        p_WUV_hi, p_WUV_lo, nullptr, p_UV, nullptr, nullptr, 1024, nullptr, 128);

    // pair stage -> E (split) [ROWS, 512]
    size_t psmem = (3 * 16 * 512 + 1024) * sizeof(float);
    cudaFuncSetAttribute(pair_kernel, cudaFuncAttributeMaxDynamicSharedMemorySize, (int)psmem);
    pair_kernel<<<B_SZ, 512, psmem>>>(p_UV, Wa, ba, be, p_E_hi, p_E_lo);

    // G4: rel = [h | E] @ WcE^T + bc -> split  [ROWS, 128], Kd=640
    gemm_mma<0,1><<<dim3(1, MB), 256, SMEM_GEMM>>>(
        p_h_hi, p_h_lo, 128, 128, p_E_hi, p_E_lo, 512,
        p_WcE_hi, p_WcE_lo, bc, nullptr, p_rel_hi, p_rel_lo, 128, nullptr, 640);

    // G5: [loc|scale|h_out] = rel @ Wstk^T + bstk, final f32 split outputs
    gemm_mma<0,2><<<dim3(3, MB), 256, SMEM_GEMM>>>(
        p_rel_hi, p_rel_lo, 128, 128, nullptr, nullptr, 0,
        p_Wstk_hi, p_Wstk_lo, p_bstk, out1, nullptr, nullptr, 0, out2, 128);
}